// round 15
// baseline (speedup 1.0000x reference)
#include <cuda_runtime.h>
#include <cuda_bf16.h>
#include <stdint.h>

// Problem constants (fixed by setup_inputs)
#define BB    32
#define SS    8192
#define CC    256
#define KK    64
#define NCOL  (BB * CC)      // 8192 columns
#define CH    8              // row chunks per column
#define CHROWS (SS / CH)     // 1024
#define CHCAP 48             // per-chunk candidate slots (mean 14.6, sd 3.8)
#define NSEL  256            // max candidates (mean 117, sd 10.7)
#define NGRP  4              // pipeline groups (8 batches each)
#define BPG   (BB / NGRP)    // 8 batches per group

// Threshold 2.1875: P(X>t)=0.0143 -> ~117 candidates/column.
#define THRESH 2.1875f

// Scratch (device globals — allocation-free per harness rules)
__device__ unsigned long long g_cand[(size_t)NCOL * CH * CHCAP];  // 25.2 MB
__device__ int                g_cnt[NCOL * CH];

__device__ __forceinline__ unsigned int fkey(float f) {
    unsigned int u = __float_as_uint(f);
    return (u & 0x80000000u) ? ~u : (u | 0x80000000u);
}

// ---------------------------------------------------------------------------
// Stream kernel (per batch-group): grid = 8b x 16tile x 8chunk = 1024 blocks.
// Identical body to the measured ~80%-BW version; b is offset by b0.
// ---------------------------------------------------------------------------
__global__ void __launch_bounds__(256, 6) stream_kernel(const float* __restrict__ x,
                                                        int b0) {
    __shared__ int scnt[16];
    const int tid = threadIdx.x;
    const int bid = blockIdx.x;
    const int h   = bid & 7;
    const int ct  = (bid >> 3) & 15;
    const int b   = b0 + (bid >> 7);

    if (tid < 16) scnt[tid] = 0;
    __syncthreads();

    const int q  = tid & 3;
    const int sr = tid >> 2;
    const float4* __restrict__ x4 = reinterpret_cast<const float4*>(x);
    const size_t base = (size_t)b * SS * (CC / 4) + ct * 4 + q
                      + (size_t)(h * CHROWS + sr) * (CC / 4);
    const int colbase = b * CC + ct * 16 + q * 4;
    const int s0 = h * CHROWS + sr;

    for (int itb = 0; itb < 4; itb++) {
        float4 v[4];
#pragma unroll
        for (int g = 0; g < 4; g++)
            v[g] = __ldcs(&x4[base + (size_t)((itb * 4 + g) * 64) * (CC / 4)]);

#pragma unroll
        for (int g = 0; g < 4; g++) {
            float m = fmaxf(fmaxf(v[g].x, v[g].y), fmaxf(v[g].z, v[g].w));
            if (m >= THRESH) {
                const int s = s0 + (itb * 4 + g) * 64;
                float vals[4] = {v[g].x, v[g].y, v[g].z, v[g].w};
#pragma unroll
                for (int l = 0; l < 4; l++) {
                    if (vals[l] >= THRESH) {
                        const int cl = q * 4 + l;
                        int pos = atomicAdd(&scnt[cl], 1);
                        if (pos < CHCAP) {
                            unsigned int key = __float_as_uint(vals[l]) | 0x80000000u;
                            g_cand[((size_t)(colbase + l) * CH + h) * CHCAP + pos] =
                                ((unsigned long long)key << 32) | (unsigned int)s;
                        }
                    }
                }
            }
        }
    }
    __syncthreads();
    if (tid < 16)
        g_cnt[(b * CC + ct * 16 + tid) * CH + h] = scnt[tid];
}

// ---------------------------------------------------------------------------
// Warp sort helpers (64-element sequences: reg lo holds e=lane, hi e=32+lane)
// ---------------------------------------------------------------------------
template <int NS>
__device__ __forceinline__ void sort64_batch(unsigned long long (&lo)[NS],
                                             unsigned long long (&hi)[NS],
                                             int lane) {
#pragma unroll
    for (int k = 2; k <= 32; k <<= 1) {
#pragma unroll
        for (int j = k >> 1; j > 0; j >>= 1) {
#pragma unroll
            for (int q = 0; q < NS; q++) {
                unsigned long long p = __shfl_xor_sync(0xffffffffu, lo[q], j);
                bool km = ((lane & k) == 0) == ((lane & j) == 0);
                lo[q] = ((lo[q] < p) == km) ? lo[q] : p;
                unsigned long long p2 = __shfl_xor_sync(0xffffffffu, hi[q], j);
                bool km2 = (((lane + 32) & k) == 0) == ((lane & j) == 0);
                hi[q] = ((hi[q] < p2) == km2) ? hi[q] : p2;
            }
        }
    }
    // k = 64: cross-reg (j=32), then ascending in-warp merge
#pragma unroll
    for (int q = 0; q < NS; q++)
        if (lo[q] > hi[q]) { unsigned long long t = lo[q]; lo[q] = hi[q]; hi[q] = t; }
#pragma unroll
    for (int j = 16; j > 0; j >>= 1) {
#pragma unroll
        for (int q = 0; q < NS; q++) {
            bool km = ((lane & j) == 0);
            unsigned long long p = __shfl_xor_sync(0xffffffffu, lo[q], j);
            lo[q] = ((lo[q] < p) == km) ? lo[q] : p;
            unsigned long long p2 = __shfl_xor_sync(0xffffffffu, hi[q], j);
            hi[q] = ((hi[q] < p2) == km) ? hi[q] : p2;
        }
    }
}

// Bitonic 64-seq -> ascending (after a half-cleaner).
__device__ __forceinline__ void bmerge64(unsigned long long& lo,
                                         unsigned long long& hi, int lane) {
    if (lo > hi) { unsigned long long t = lo; lo = hi; hi = t; }
#pragma unroll
    for (int j = 16; j > 0; j >>= 1) {
        bool km = ((lane & j) == 0);
        unsigned long long p = __shfl_xor_sync(0xffffffffu, lo, j);
        lo = ((lo < p) == km) ? lo : p;
        unsigned long long p2 = __shfl_xor_sync(0xffffffffu, hi, j);
        hi = ((hi < p2) == km) ? hi : p2;
    }
}

__device__ __forceinline__ unsigned long long max64(unsigned long long a,
                                                    unsigned long long b) {
    return a > b ? a : b;
}

// Ascending sort of a 64-seq of 32-bit tokens.
__device__ __forceinline__ void sort64_u32(unsigned int& a, unsigned int& b,
                                           int lane) {
#pragma unroll
    for (int k = 2; k <= 32; k <<= 1) {
#pragma unroll
        for (int j = k >> 1; j > 0; j >>= 1) {
            unsigned int p = __shfl_xor_sync(0xffffffffu, a, j);
            bool km = ((lane & k) == 0) == ((lane & j) == 0);
            a = ((a < p) == km) ? a : p;
            unsigned int p2 = __shfl_xor_sync(0xffffffffu, b, j);
            bool km2 = (((lane + 32) & k) == 0) == ((lane & j) == 0);
            b = ((b < p2) == km2) ? b : p2;
        }
    }
    if (a > b) { unsigned int t = a; a = b; b = t; }
#pragma unroll
    for (int j = 16; j > 0; j >>= 1) {
        bool km = ((lane & j) == 0);
        unsigned int p = __shfl_xor_sync(0xffffffffu, a, j);
        a = ((a < p) == km) ? a : p;
        unsigned int p2 = __shfl_xor_sync(0xffffffffu, b, j);
        b = ((b < p2) == km) ? b : p2;
    }
}

// ---------------------------------------------------------------------------
// Select kernel (per batch-group): 64 threads (2 warps), one column per warp.
// col = b0*CC + blockIdx.x*2 + w. Body identical to the measured version.
// ---------------------------------------------------------------------------
__global__ void __launch_bounds__(64) select_kernel(const float* __restrict__ x,
                                                    float* __restrict__ out,
                                                    int b0) {
    __shared__ unsigned long long sbuf[2][NSEL];    // 4 KB
    __shared__ int s_fail[2];
    __shared__ int s_nfail;
    __shared__ int sred[64];

    const int tid  = threadIdx.x;
    const int w    = tid >> 5;
    const int lane = tid & 31;
    const int col  = b0 * CC + blockIdx.x * 2 + w;
    const int b    = col >> 8;
    const int c    = col & (CC - 1);

    if (tid == 0) s_nfail = 0;
    __syncthreads();

    // counts + exclusive scan over 8 chunks (lanes 0..7)
    int cnt = (lane < CH) ? g_cnt[col * CH + lane] : 0;
    unsigned int ovf = __ballot_sync(0xffffffffu, (lane < CH) && (cnt > CHCAP));
    int sc = cnt;
#pragma unroll
    for (int d = 1; d < 8; d <<= 1) {
        int t2 = __shfl_up_sync(0xffffffffu, sc, d);
        if (lane >= d) sc += t2;
    }
    const int n = __shfl_sync(0xffffffffu, sc, CH - 1);
    const int excl = sc - cnt;

    if (n >= KK && n <= NSEL && ovf == 0u) {
        // ---- compact chunk segments into smem ----
#pragma unroll
        for (int h = 0; h < CH; h++) {
            int chn = __shfl_sync(0xffffffffu, cnt, h);
            int bs  = __shfl_sync(0xffffffffu, excl, h);
            const unsigned long long* src = &g_cand[((size_t)col * CH + h) * CHCAP];
            for (int i = lane; i < chn; i += 32)
                sbuf[w][bs + i] = src[i];
        }
        __syncwarp();

        unsigned long long t_lo, t_hi;      // top-64 multiset (order-free)

        if (n <= 128) {
            unsigned long long lo[2], hi[2];
#pragma unroll
            for (int q = 0; q < 2; q++) {
                int e0 = q * 64 + lane;
                int e1 = q * 64 + 32 + lane;
                lo[q] = (e0 < n) ? sbuf[w][e0] : 0ull;
                hi[q] = (e1 < n) ? sbuf[w][e1] : 0ull;
            }
            sort64_batch<2>(lo, hi, lane);
            t_lo = max64(lo[0], __shfl_xor_sync(0xffffffffu, hi[1], 31));
            t_hi = max64(hi[0], __shfl_xor_sync(0xffffffffu, lo[1], 31));
        } else {
            unsigned long long lo[4], hi[4];
#pragma unroll
            for (int q = 0; q < 4; q++) {
                int e0 = q * 64 + lane;
                int e1 = q * 64 + 32 + lane;
                lo[q] = (e0 < n) ? sbuf[w][e0] : 0ull;
                hi[q] = (e1 < n) ? sbuf[w][e1] : 0ull;
            }
            sort64_batch<4>(lo, hi, lane);
            unsigned long long m_lo = max64(lo[0], __shfl_xor_sync(0xffffffffu, hi[1], 31));
            unsigned long long m_hi = max64(hi[0], __shfl_xor_sync(0xffffffffu, lo[1], 31));
            bmerge64(m_lo, m_hi, lane);
            unsigned long long p_lo = max64(lo[2], __shfl_xor_sync(0xffffffffu, hi[3], 31));
            unsigned long long p_hi = max64(hi[2], __shfl_xor_sync(0xffffffffu, lo[3], 31));
            bmerge64(p_lo, p_hi, lane);
            t_lo = max64(m_lo, __shfl_xor_sync(0xffffffffu, p_hi, 31));
            t_hi = max64(m_hi, __shfl_xor_sync(0xffffffffu, p_lo, 31));
        }

        // ---- index order: 32-bit token sort (s<<7 | pos), s distinct ----
        unsigned int tok0 = (((unsigned int)t_lo & 0x1FFFu) << 7) | (unsigned int)lane;
        unsigned int tok1 = (((unsigned int)t_hi & 0x1FFFu) << 7) | (unsigned int)(32 + lane);
        sort64_u32(tok0, tok1, lane);

        // ---- gather keys by pos and write out[b][f][c] ----
        unsigned int klo = (unsigned int)(t_lo >> 32);
        unsigned int khi = (unsigned int)(t_hi >> 32);

        int p0 = tok0 & 127;
        unsigned int g0a = __shfl_sync(0xffffffffu, klo, p0 & 31);
        unsigned int g0b = __shfl_sync(0xffffffffu, khi, p0 & 31);
        unsigned int key0 = (p0 < 32) ? g0a : g0b;

        int p1 = tok1 & 127;
        unsigned int g1a = __shfl_sync(0xffffffffu, klo, p1 & 31);
        unsigned int g1b = __shfl_sync(0xffffffffu, khi, p1 & 31);
        unsigned int key1 = (p1 < 32) ? g1a : g1b;

        out[((size_t)b * KK + lane) * CC + c]      = __uint_as_float(key0 & 0x7FFFFFFFu);
        out[((size_t)b * KK + 32 + lane) * CC + c] = __uint_as_float(key1 & 0x7FFFFFFFu);
    } else {
        if (lane == 0) {
            int i = atomicAdd(&s_nfail, 1);
            s_fail[i] = col;
        }
    }

    // ---- block-cooperative exact epilogue (expected no-op; sigma>=5 events) ----
    __syncthreads();
    const int nf = s_nfail;
    for (int f = 0; f < nf; f++) {
        const int fcol = s_fail[f];
        const int fb = fcol >> 8;
        const int fc = fcol & (CC - 1);
        const size_t xbase = (size_t)fb * SS * CC + fc;

        unsigned long long V = 0;
        for (int bit = 63; bit >= 0; bit--) {
            unsigned long long cand = V | (1ull << bit);
            int local = 0;
            for (int s = tid; s < SS; s += 64) {
                float fv = x[xbase + (size_t)s * CC];
                unsigned long long comp =
                    ((unsigned long long)fkey(fv) << 32) | (unsigned int)s;
                local += (comp >= cand);
            }
            sred[tid] = local;
            __syncthreads();
            for (int st = 32; st > 0; st >>= 1) {
                if (tid < st) sred[tid] += sred[tid + st];
                __syncthreads();
            }
            int cntv = sred[0];
            __syncthreads();
            if (cntv >= KK) V = cand;
        }

        const int per = SS / 64;            // 128
        int lcnt = 0;
        for (int k2 = 0; k2 < per; k2++) {
            int s = tid * per + k2;
            float fv = x[xbase + (size_t)s * CC];
            unsigned long long comp =
                ((unsigned long long)fkey(fv) << 32) | (unsigned int)s;
            lcnt += (comp >= V);
        }
        sred[tid] = lcnt;
        __syncthreads();
        for (int off = 1; off < 64; off <<= 1) {
            int vv = sred[tid];
            int ww = (tid >= off) ? sred[tid - off] : 0;
            __syncthreads();
            sred[tid] = vv + ww;
            __syncthreads();
        }
        int basep = sred[tid] - lcnt;
        for (int k2 = 0; k2 < per; k2++) {
            int s = tid * per + k2;
            float fv = x[xbase + (size_t)s * CC];
            unsigned long long comp =
                ((unsigned long long)fkey(fv) << 32) | (unsigned int)s;
            if (comp >= V) {
                if (basep < KK)
                    out[((size_t)fb * KK + basep) * CC + fc] = fv;
                basep++;
            }
        }
        __syncthreads();
    }
}

// ---------------------------------------------------------------------------
// Two-stream pipeline: stream groups on the capture stream, selects on a
// side stream gated by events (standard capturable fork/join pattern).
// Stream/event objects are created on the FIRST call (the uncaptured
// correctness run) and reused by the captured graph.
// ---------------------------------------------------------------------------
static cudaStream_t g_s2 = nullptr;
static cudaEvent_t  g_evF[NGRP];
static cudaEvent_t  g_evJ = nullptr;

extern "C" void kernel_launch(void* const* d_in, const int* in_sizes, int n_in,
                              void* d_out, int out_size) {
    const float* x = (const float*)d_in[0];
    float* out = (float*)d_out;

    if (g_s2 == nullptr) {
        cudaStreamCreateWithFlags(&g_s2, cudaStreamNonBlocking);
        for (int g = 0; g < NGRP; g++)
            cudaEventCreateWithFlags(&g_evF[g], cudaEventDisableTiming);
        cudaEventCreateWithFlags(&g_evJ, cudaEventDisableTiming);
    }

    // Streams back-to-back on the main (capture) stream; fork per group.
    for (int g = 0; g < NGRP; g++) {
        stream_kernel<<<BPG * 16 * CH, 256>>>(x, g * BPG);   // 1024 blocks
        cudaEventRecord(g_evF[g], 0);
    }
    for (int g = 0; g < NGRP; g++) {
        cudaStreamWaitEvent(g_s2, g_evF[g], 0);
        select_kernel<<<BPG * CC / 2, 64, 0, g_s2>>>(x, out, g * BPG);  // 1024 blocks
    }
    cudaEventRecord(g_evJ, g_s2);
    cudaStreamWaitEvent(0, g_evJ, 0);
}

// round 17
// speedup vs baseline: 1.2125x; 1.2125x over previous
#include <cuda_runtime.h>
#include <cuda_bf16.h>
#include <stdint.h>

// Problem constants (fixed by setup_inputs)
#define BB    32
#define SS    8192
#define CC    256
#define KK    64
#define NCOL  (BB * CC)      // 8192 columns
#define CH    4              // row chunks per column
#define CHROWS (SS / CH)     // 2048
#define CHCAP 64             // slots per chunk (mean 29.3, sd 5.4 -> 6.4 sigma)
#define NSLOT (CH * CHCAP)   // 256 dense slots per column; run q == chunk q

// Threshold 2.1875: P(X>t)=0.0143 -> ~117 candidates/column.
#define THRESH 2.1875f

// Scratch (device globals — allocation-free per harness rules)
__device__ unsigned long long g_cand[(size_t)NCOL * NSLOT];   // 16.8 MB
__device__ int                g_cnt[NCOL * CH];

__device__ __forceinline__ unsigned int fkey(float f) {
    unsigned int u = __float_as_uint(f);
    return (u & 0x80000000u) ? ~u : (u | 0x80000000u);
}

// ---------------------------------------------------------------------------
// Stream kernel: grid = 32b x 16tile x 4chunk = 2048 blocks. Same measured
// ~80%-BW body; candidates land in the dense per-column run layout.
// ---------------------------------------------------------------------------
__global__ void __launch_bounds__(256, 6) stream_kernel(const float* __restrict__ x) {
    __shared__ int scnt[16];
    const int tid = threadIdx.x;
    const int bid = blockIdx.x;
    const int h   = bid & 3;
    const int ct  = (bid >> 2) & 15;
    const int b   = bid >> 6;

    if (tid < 16) scnt[tid] = 0;
    __syncthreads();

    const int q  = tid & 3;
    const int sr = tid >> 2;
    const float4* __restrict__ x4 = reinterpret_cast<const float4*>(x);
    const size_t base = (size_t)b * SS * (CC / 4) + ct * 4 + q
                      + (size_t)(h * CHROWS + sr) * (CC / 4);
    const int colbase = b * CC + ct * 16 + q * 4;
    const int s0 = h * CHROWS + sr;

    for (int itb = 0; itb < 8; itb++) {
        float4 v[4];
#pragma unroll
        for (int g = 0; g < 4; g++)
            v[g] = __ldcs(&x4[base + (size_t)((itb * 4 + g) * 64) * (CC / 4)]);

#pragma unroll
        for (int g = 0; g < 4; g++) {
            float m = fmaxf(fmaxf(v[g].x, v[g].y), fmaxf(v[g].z, v[g].w));
            if (m >= THRESH) {
                const int s = s0 + (itb * 4 + g) * 64;
                float vals[4] = {v[g].x, v[g].y, v[g].z, v[g].w};
#pragma unroll
                for (int l = 0; l < 4; l++) {
                    if (vals[l] >= THRESH) {
                        const int cl = q * 4 + l;
                        int pos = atomicAdd(&scnt[cl], 1);
                        if (pos < CHCAP) {
                            unsigned int key = __float_as_uint(vals[l]) | 0x80000000u;
                            g_cand[(size_t)(colbase + l) * NSLOT + h * CHCAP + pos] =
                                ((unsigned long long)key << 32) | (unsigned int)s;
                        }
                    }
                }
            }
        }
    }
    __syncthreads();
    if (tid < 16)
        g_cnt[(b * CC + ct * 16 + tid) * CH + h] = scnt[tid];
}

// ---------------------------------------------------------------------------
// Warp sort helpers (64-element sequences: reg lo holds e=lane, hi e=32+lane)
// ---------------------------------------------------------------------------
template <int NS>
__device__ __forceinline__ void sort64_batch(unsigned long long (&lo)[NS],
                                             unsigned long long (&hi)[NS],
                                             int lane) {
#pragma unroll
    for (int k = 2; k <= 32; k <<= 1) {
#pragma unroll
        for (int j = k >> 1; j > 0; j >>= 1) {
#pragma unroll
            for (int q = 0; q < NS; q++) {
                unsigned long long p = __shfl_xor_sync(0xffffffffu, lo[q], j);
                bool km = ((lane & k) == 0) == ((lane & j) == 0);
                lo[q] = ((lo[q] < p) == km) ? lo[q] : p;
                unsigned long long p2 = __shfl_xor_sync(0xffffffffu, hi[q], j);
                bool km2 = (((lane + 32) & k) == 0) == ((lane & j) == 0);
                hi[q] = ((hi[q] < p2) == km2) ? hi[q] : p2;
            }
        }
    }
    // k = 64: cross-reg (j=32), then ascending in-warp merge
#pragma unroll
    for (int q = 0; q < NS; q++)
        if (lo[q] > hi[q]) { unsigned long long t = lo[q]; lo[q] = hi[q]; hi[q] = t; }
#pragma unroll
    for (int j = 16; j > 0; j >>= 1) {
#pragma unroll
        for (int q = 0; q < NS; q++) {
            bool km = ((lane & j) == 0);
            unsigned long long p = __shfl_xor_sync(0xffffffffu, lo[q], j);
            lo[q] = ((lo[q] < p) == km) ? lo[q] : p;
            unsigned long long p2 = __shfl_xor_sync(0xffffffffu, hi[q], j);
            hi[q] = ((hi[q] < p2) == km) ? hi[q] : p2;
        }
    }
}

// Bitonic 64-seq -> ascending (after a half-cleaner).
__device__ __forceinline__ void bmerge64(unsigned long long& lo,
                                         unsigned long long& hi, int lane) {
    if (lo > hi) { unsigned long long t = lo; lo = hi; hi = t; }
#pragma unroll
    for (int j = 16; j > 0; j >>= 1) {
        bool km = ((lane & j) == 0);
        unsigned long long p = __shfl_xor_sync(0xffffffffu, lo, j);
        lo = ((lo < p) == km) ? lo : p;
        unsigned long long p2 = __shfl_xor_sync(0xffffffffu, hi, j);
        hi = ((hi < p2) == km) ? hi : p2;
    }
}

__device__ __forceinline__ unsigned long long max64(unsigned long long a,
                                                    unsigned long long b) {
    return a > b ? a : b;
}

// Ascending sort of a 64-seq of 32-bit tokens.
__device__ __forceinline__ void sort64_u32(unsigned int& a, unsigned int& b,
                                           int lane) {
#pragma unroll
    for (int k = 2; k <= 32; k <<= 1) {
#pragma unroll
        for (int j = k >> 1; j > 0; j >>= 1) {
            unsigned int p = __shfl_xor_sync(0xffffffffu, a, j);
            bool km = ((lane & k) == 0) == ((lane & j) == 0);
            a = ((a < p) == km) ? a : p;
            unsigned int p2 = __shfl_xor_sync(0xffffffffu, b, j);
            bool km2 = (((lane + 32) & k) == 0) == ((lane & j) == 0);
            b = ((b < p2) == km2) ? b : p2;
        }
    }
    if (a > b) { unsigned int t = a; a = b; b = t; }
#pragma unroll
    for (int j = 16; j > 0; j >>= 1) {
        bool km = ((lane & j) == 0);
        unsigned int p = __shfl_xor_sync(0xffffffffu, a, j);
        a = ((a < p) == km) ? a : p;
        unsigned int p2 = __shfl_xor_sync(0xffffffffu, b, j);
        b = ((b < p2) == km) ? b : p2;
    }
}

// ---------------------------------------------------------------------------
// Select kernel: 64 threads (2 warps), one column per warp. NO smem staging:
// each warp loads its column's 256 dense slots straight into registers
// (coalesced, MLP=8), zero-pads by count, then partial top-64 + token sort.
// ---------------------------------------------------------------------------
__global__ void __launch_bounds__(64) select_kernel(const float* __restrict__ x,
                                                    float* __restrict__ out) {
    __shared__ int s_fail[2];
    __shared__ int s_nfail;
    __shared__ int sred[64];

    const int tid  = threadIdx.x;
    const int w    = tid >> 5;
    const int lane = tid & 31;
    const int col  = blockIdx.x * 2 + w;
    const int b    = col >> 8;
    const int c    = col & (CC - 1);

    if (tid == 0) s_nfail = 0;
    __syncthreads();

    // per-chunk counts (lanes 0..3), total via butterfly, overflow check
    int cnt = (lane < CH) ? g_cnt[col * CH + lane] : 0;
    unsigned int ovf = __ballot_sync(0xffffffffu, (lane < CH) && (cnt > CHCAP));
    int n = cnt;
#pragma unroll
    for (int j = 1; j < 32; j <<= 1) n += __shfl_xor_sync(0xffffffffu, n, j);

    if (n >= KK && ovf == 0u) {
        const unsigned long long* __restrict__ src = &g_cand[(size_t)col * NSLOT];

        // ---- direct register load: run q == chunk q (64 slots each) ----
        unsigned long long lo[4], hi[4];
#pragma unroll
        for (int q = 0; q < 4; q++) {
            int cq = __shfl_sync(0xffffffffu, cnt, q);
            lo[q] = (lane < cq)      ? src[q * 64 + lane]      : 0ull;
            hi[q] = (32 + lane < cq) ? src[q * 64 + 32 + lane] : 0ull;
        }

        sort64_batch<4>(lo, hi, lane);

        // tournament of half-cleaners -> top-64 multiset
        unsigned long long m_lo = max64(lo[0], __shfl_xor_sync(0xffffffffu, hi[1], 31));
        unsigned long long m_hi = max64(hi[0], __shfl_xor_sync(0xffffffffu, lo[1], 31));
        bmerge64(m_lo, m_hi, lane);
        unsigned long long p_lo = max64(lo[2], __shfl_xor_sync(0xffffffffu, hi[3], 31));
        unsigned long long p_hi = max64(hi[2], __shfl_xor_sync(0xffffffffu, lo[3], 31));
        bmerge64(p_lo, p_hi, lane);
        unsigned long long t_lo = max64(m_lo, __shfl_xor_sync(0xffffffffu, p_hi, 31));
        unsigned long long t_hi = max64(m_hi, __shfl_xor_sync(0xffffffffu, p_lo, 31));

        // ---- index order: 32-bit token sort (s<<7 | pos), s distinct ----
        unsigned int tok0 = (((unsigned int)t_lo & 0x1FFFu) << 7) | (unsigned int)lane;
        unsigned int tok1 = (((unsigned int)t_hi & 0x1FFFu) << 7) | (unsigned int)(32 + lane);
        sort64_u32(tok0, tok1, lane);

        // ---- gather keys by pos and write out[b][f][c] ----
        unsigned int klo = (unsigned int)(t_lo >> 32);
        unsigned int khi = (unsigned int)(t_hi >> 32);

        int p0 = tok0 & 127;
        unsigned int g0a = __shfl_sync(0xffffffffu, klo, p0 & 31);
        unsigned int g0b = __shfl_sync(0xffffffffu, khi, p0 & 31);
        unsigned int key0 = (p0 < 32) ? g0a : g0b;

        int p1 = tok1 & 127;
        unsigned int g1a = __shfl_sync(0xffffffffu, klo, p1 & 31);
        unsigned int g1b = __shfl_sync(0xffffffffu, khi, p1 & 31);
        unsigned int key1 = (p1 < 32) ? g1a : g1b;

        out[((size_t)b * KK + lane) * CC + c]      = __uint_as_float(key0 & 0x7FFFFFFFu);
        out[((size_t)b * KK + 32 + lane) * CC + c] = __uint_as_float(key1 & 0x7FFFFFFFu);
    } else {
        if (lane == 0) {
            int i = atomicAdd(&s_nfail, 1);
            s_fail[i] = col;
        }
    }

    // ---- block-cooperative exact epilogue (expected no-op; sigma>=5 events) ----
    __syncthreads();
    const int nf = s_nfail;
    for (int f = 0; f < nf; f++) {
        const int fcol = s_fail[f];
        const int fb = fcol >> 8;
        const int fc = fcol & (CC - 1);
        const size_t xbase = (size_t)fb * SS * CC + fc;

        unsigned long long V = 0;
        for (int bit = 63; bit >= 0; bit--) {
            unsigned long long cand = V | (1ull << bit);
            int local = 0;
            for (int s = tid; s < SS; s += 64) {
                float fv = x[xbase + (size_t)s * CC];
                unsigned long long comp =
                    ((unsigned long long)fkey(fv) << 32) | (unsigned int)s;
                local += (comp >= cand);
            }
            sred[tid] = local;
            __syncthreads();
            for (int st = 32; st > 0; st >>= 1) {
                if (tid < st) sred[tid] += sred[tid + st];
                __syncthreads();
            }
            int cntv = sred[0];
            __syncthreads();
            if (cntv >= KK) V = cand;
        }

        const int per = SS / 64;            // 128
        int lcnt = 0;
        for (int k2 = 0; k2 < per; k2++) {
            int s = tid * per + k2;
            float fv = x[xbase + (size_t)s * CC];
            unsigned long long comp =
                ((unsigned long long)fkey(fv) << 32) | (unsigned int)s;
            lcnt += (comp >= V);
        }
        sred[tid] = lcnt;
        __syncthreads();
        for (int off = 1; off < 64; off <<= 1) {
            int vv = sred[tid];
            int ww = (tid >= off) ? sred[tid - off] : 0;
            __syncthreads();
            sred[tid] = vv + ww;
            __syncthreads();
        }
        int basep = sred[tid] - lcnt;
        for (int k2 = 0; k2 < per; k2++) {
            int s = tid * per + k2;
            float fv = x[xbase + (size_t)s * CC];
            unsigned long long comp =
                ((unsigned long long)fkey(fv) << 32) | (unsigned int)s;
            if (comp >= V) {
                if (basep < KK)
                    out[((size_t)fb * KK + basep) * CC + fc] = fv;
                basep++;
            }
        }
        __syncthreads();
    }
}

extern "C" void kernel_launch(void* const* d_in, const int* in_sizes, int n_in,
                              void* d_out, int out_size) {
    const float* x = (const float*)d_in[0];
    float* out = (float*)d_out;

    stream_kernel<<<BB * 16 * CH, 256>>>(x);     // 2048 blocks
    select_kernel<<<NCOL / 2, 64>>>(x, out);     // 4096 blocks
}